// round 3
// baseline (speedup 1.0000x reference)
#include <cuda_runtime.h>
#include <math_constants.h>
#include <stdint.h>

#define B  32
#define N  8192
#define K  128
#define PS 32

#define BINS  2048
#define CAPK  1024
#define SRANK 5          // sample rank for threshold estimate (~rank 160 of 8192)

typedef unsigned long long u64;

// Scratch (allocation-free rule: __device__ globals)
__device__ int   g_fps_idx[B * K];
__device__ float g_centers[B * K * 3];
__device__ int   g_knn[B * K * PS];

// ---------------------------------------------------------------------------
// f32x2 packed helpers (one fma-pipe instr = 2 IEEE .rn ops, bit-identical)
// ---------------------------------------------------------------------------
__device__ __forceinline__ u64 pack2(float lo, float hi) {
    u64 r; asm("mov.b64 %0, {%1, %2};" : "=l"(r) : "f"(lo), "f"(hi)); return r;
}
__device__ __forceinline__ float2 unpack2(u64 v) {
    float2 f; asm("mov.b64 {%0, %1}, %2;" : "=f"(f.x), "=f"(f.y) : "l"(v)); return f;
}
__device__ __forceinline__ u64 add2(u64 a, u64 b) {
    u64 d; asm("add.rn.f32x2 %0, %1, %2;" : "=l"(d) : "l"(a), "l"(b)); return d;
}
__device__ __forceinline__ u64 mul2(u64 a, u64 b) {
    u64 d; asm("mul.rn.f32x2 %0, %1, %2;" : "=l"(d) : "l"(a), "l"(b)); return d;
}
__device__ __forceinline__ u64 fma2(u64 a, u64 b, u64 c) {
    u64 d; asm("fma.rn.f32x2 %0, %1, %2, %3;" : "=l"(d) : "l"(a), "l"(b), "l"(c)); return d;
}

// ---------------------------------------------------------------------------
// FPS: one block per batch, 1024 threads, 8 points/thread, ONE barrier/iter.
// argmax via value REDUX then u64 atomicMax of (val_bits<<32)|(~idx):
// max value, min index on ties == jnp.argmax first-occurrence.
// ---------------------------------------------------------------------------
extern "C" __global__ void __launch_bounds__(1024, 1)
fps_kernel(const float* __restrict__ points) {
    extern __shared__ float pts[];      // [N*3] = 96KB
    __shared__ u64 s_key[K];

    const int b = blockIdx.x;
    const int t = threadIdx.x;
    const float* gp = points + (size_t)b * N * 3;

    for (int i = t; i < N * 3; i += 1024) pts[i] = gp[i];
    if (t < K) s_key[t] = 0ull;
    __syncthreads();

    u64 px2[4], py2[4], pz2[4];
    float md[8];
#pragma unroll
    for (int j = 0; j < 4; j++) {
        int nlo = t + (2 * j) * 1024;
        int nhi = t + (2 * j + 1) * 1024;
        px2[j] = pack2(pts[3 * nlo + 0], pts[3 * nhi + 0]);
        py2[j] = pack2(pts[3 * nlo + 1], pts[3 * nhi + 1]);
        pz2[j] = pack2(pts[3 * nlo + 2], pts[3 * nhi + 2]);
        md[2 * j] = CUDART_INF_F; md[2 * j + 1] = CUDART_INF_F;
    }

    int cur = 0;
    for (int k = 0; k < K; k++) {
        float cx = pts[3 * cur + 0];
        float cy = pts[3 * cur + 1];
        float cz = pts[3 * cur + 2];
        if (t == 0) {
            g_fps_idx[b * K + k] = cur;
            g_centers[(b * K + k) * 3 + 0] = cx;
            g_centers[(b * K + k) * 3 + 1] = cy;
            g_centers[(b * K + k) * 3 + 2] = cz;
        }
        u64 nc2x = pack2(-cx, -cx);
        u64 nc2y = pack2(-cy, -cy);
        u64 nc2z = pack2(-cz, -cz);
#pragma unroll
        for (int j = 0; j < 4; j++) {
            u64 dx = add2(px2[j], nc2x);
            u64 dy = add2(py2[j], nc2y);
            u64 dz = add2(pz2[j], nc2z);
            u64 d  = mul2(dx, dx);
            d = fma2(dy, dy, d);
            d = fma2(dz, dz, d);
            float2 f = unpack2(d);
            md[2 * j]     = fminf(md[2 * j],     f.x);
            md[2 * j + 1] = fminf(md[2 * j + 1], f.y);
        }
        float tv = fmaxf(fmaxf(fmaxf(md[0], md[1]), fmaxf(md[2], md[3])),
                         fmaxf(fmaxf(md[4], md[5]), fmaxf(md[6], md[7])));
        // nonneg float bits are order-preserving as uint
        unsigned tb = __float_as_uint(tv);
        unsigned wv = __reduce_max_sync(0xffffffffu, tb);
        if (tb == wv) {
            int li = 0x7fffffff;
#pragma unroll
            for (int s = 0; s < 8; s++)
                if (__float_as_uint(md[s]) == wv) li = min(li, t + s * 1024);
            u64 kk = ((u64)wv << 32) | (unsigned)(0xffffffffu - li);
            atomicMax(&s_key[k], kk);
        }
        __syncthreads();
        cur = (int)(0xffffffffu - (unsigned)s_key[k]);
    }
}

// ---------------------------------------------------------------------------
// KNN: one row per CTA, 256 threads, 32 keys/thread in REGISTERS.
// No per-point histogram atomics: sample-based threshold + ballot count +
// sparse collect + stable rank sort. Exact fallback if candidates overflow.
// ---------------------------------------------------------------------------
__device__ __forceinline__ unsigned f2key(float f) {
    unsigned bits = __float_as_uint(f);
    return (bits & 0x80000000u) ? ~bits : (bits | 0x80000000u);
}

extern "C" __global__ void __launch_bounds__(256)
knn_kernel(const float* __restrict__ points) {
    __shared__ unsigned s_hist[BINS];     // 8KB (sample histogram)
    __shared__ int      s_cidx[CAPK];     // 4KB
    __shared__ unsigned s_ckey[CAPK];     // 4KB
    __shared__ unsigned s_wsum[8];
    __shared__ int      s_T;
    __shared__ int      s_cnt;
    __shared__ u64      s_min;

    const int row = blockIdx.x;     // b*K + k
    const int b   = row >> 7;
    const int t   = threadIdx.x;
    const int lane = t & 31, w = t >> 5;
    const float* gp = points + (size_t)b * N * 3;

    const float cx = g_centers[row * 3 + 0];
    const float cy = g_centers[row * 3 + 1];
    const float cz = g_centers[row * 3 + 2];
    const float cc = cx * cx + cy * cy + cz * cz;

    for (int i = t; i < BINS; i += 256) s_hist[i] = 0u;
    if (t == 0) s_cnt = 0;
    __syncthreads();

    // Pass 1: all keys into registers (d2 form identical to reference)
    unsigned keyr[32];
#pragma unroll
    for (int j = 0; j < 32; j++) {
        int n = t + j * 256;
        float px = gp[3 * n + 0], py = gp[3 * n + 1], pz = gp[3 * n + 2];
        float pp  = px * px + py * py + pz * pz;
        float dot = cx * px + cy * py + cz * pz;
        float d2  = (cc + pp) - 2.0f * dot;
        keyr[j] = f2key(d2);
    }

    // Sample histogram: one point per thread (n = t, i.e. keyr[0])
    atomicAdd(&s_hist[keyr[0] >> 21], 1u);
    __syncthreads();

    // Threshold bin T: first bin where cumulative sample count >= SRANK
    {
        unsigned c8[8], seg = 0;
#pragma unroll
        for (int i = 0; i < 8; i++) { c8[i] = s_hist[t * 8 + i]; seg += c8[i]; }
        unsigned pre = seg;
#pragma unroll
        for (int off = 1; off < 32; off <<= 1) {
            unsigned v = __shfl_up_sync(0xffffffffu, pre, off);
            if (lane >= off) pre += v;
        }
        if (lane == 31) s_wsum[w] = pre;
        __syncthreads();
        unsigned wbase = 0;
        for (int i = 0; i < w; i++) wbase += s_wsum[i];
        unsigned excl = wbase + pre - seg;
        if (excl < SRANK && excl + seg >= SRANK) {
            unsigned cum = excl;
            int Tb = -1;
#pragma unroll
            for (int i = 0; i < 8; i++) {
                cum += c8[i];
                if (Tb < 0 && cum >= SRANK) Tb = t * 8 + i;
            }
            s_T = Tb;
        }
        __syncthreads();
    }
    int T = s_T;

    // Count loop: grow T (x2 in d2 per +8 bins) until >= PS survivors
    int cnt;
    while (true) {
        int c = 0;
#pragma unroll
        for (int j = 0; j < 32; j++) c += ((int)(keyr[j] >> 21) <= T);
        c = __reduce_add_sync(0xffffffffu, c);
        if (lane == 0) atomicAdd(&s_cnt, c);
        __syncthreads();
        cnt = s_cnt;
        __syncthreads();
        if (cnt >= PS) break;
        T = min(2047, T + 8);
        if (t == 0) s_cnt = 0;
        __syncthreads();
    }

    if (t == 0) s_cnt = 0;
    __syncthreads();
    int* out = &g_knn[row * PS];

    if (cnt <= CAPK) {
        // Collect survivors (only ~cnt atomics)
#pragma unroll
        for (int j = 0; j < 32; j++) {
            if ((int)(keyr[j] >> 21) <= T) {
                int pos = atomicAdd(&s_cnt, 1);
                s_cidx[pos] = t + j * 256;
                s_ckey[pos] = keyr[j];
            }
        }
        __syncthreads();
        const int C = s_cnt;
        // Stable rank sort: rank = #{(key,idx) strictly smaller}
        for (int jj = t; jj < C; jj += 256) {
            unsigned kj = s_ckey[jj];
            int      nj = s_cidx[jj];
            int r = 0;
            for (int m = 0; m < C; m++) {
                unsigned km = s_ckey[m];
                r += (km < kj) || (km == kj && s_cidx[m] < nj);
            }
            if (r < PS) out[r] = nj;
        }
    } else {
        // Exact fallback (never expected): 32 sequential lexicographic mins
        u64 lastv = 0ull;   // all valid v=(key<<32)|n are > 0
        for (int sel = 0; sel < PS; sel++) {
            if (t == 0) s_min = 0xffffffffffffffffull;
            __syncthreads();
            u64 best = 0xffffffffffffffffull;
#pragma unroll
            for (int j = 0; j < 32; j++) {
                u64 v = ((u64)keyr[j] << 32) | (unsigned)(t + j * 256);
                if (v > lastv && v < best) best = v;
            }
#pragma unroll
            for (int off = 16; off; off >>= 1) {
                u64 o = __shfl_down_sync(0xffffffffu, best, off);
                best = o < best ? o : best;
            }
            if (lane == 0) atomicMin(&s_min, best);
            __syncthreads();
            u64 m = s_min;
            if (t == 0) out[sel] = (int)(unsigned)(m & 0xffffffffu);
            lastv = m;
            __syncthreads();
        }
    }
}

// ---------------------------------------------------------------------------
// Epilogues — handle both plausible output layouts.
// ---------------------------------------------------------------------------
extern "C" __global__ void epilogue_i32(int* __restrict__ out, int out_size) {
    int i = blockIdx.x * 256 + threadIdx.x;
    if (i < out_size && i < B * K * PS) out[i] = g_knn[i];
}

extern "C" __global__ void epilogue_f32(float* __restrict__ out, int out_size) {
    int i = blockIdx.x * 256 + threadIdx.x;
    if (i >= out_size) return;
    if (i < B * K * PS) {
        out[i] = (float)g_knn[i];
    } else if (i < B * K * PS + B * K * 3) {
        out[i] = g_centers[i - B * K * PS];
    }
}

// ---------------------------------------------------------------------------
extern "C" void kernel_launch(void* const* d_in, const int* in_sizes, int n_in,
                              void* d_out, int out_size) {
    (void)in_sizes; (void)n_in;
    const float* points = (const float*)d_in[0];

    const int fps_smem = N * 3 * (int)sizeof(float);
    cudaFuncSetAttribute(fps_kernel,
                         cudaFuncAttributeMaxDynamicSharedMemorySize, fps_smem);

    fps_kernel<<<B, 1024, fps_smem>>>(points);
    knn_kernel<<<B * K, 256>>>(points);

    if (out_size == B * K * PS) {
        int total = B * K * PS;
        epilogue_i32<<<(total + 255) / 256, 256>>>((int*)d_out, out_size);
    } else {
        int total = B * K * PS + B * K * 3;
        int n = total < out_size ? out_size : total;
        epilogue_f32<<<(n + 255) / 256, 256>>>((float*)d_out, out_size);
    }
}

// round 4
// speedup vs baseline: 1.9066x; 1.9066x over previous
#include <cuda_runtime.h>
#include <math_constants.h>
#include <stdint.h>

#define B  32
#define N  8192
#define K  128
#define PS 32

#define CPW  4            // centers per warp (KNN)
#define TILE 2048         // points per smem tile (KNN)

typedef unsigned long long u64;

// Scratch (allocation-free rule: __device__ globals)
__device__ int   g_fps_idx[B * K];
__device__ float g_centers[B * K * 3];
__device__ int   g_knn[B * K * PS];

// ---------------------------------------------------------------------------
// f32x2 packed helpers (one fma-pipe instr = 2 IEEE .rn ops, bit-identical)
// ---------------------------------------------------------------------------
__device__ __forceinline__ u64 pack2(float lo, float hi) {
    u64 r; asm("mov.b64 %0, {%1, %2};" : "=l"(r) : "f"(lo), "f"(hi)); return r;
}
__device__ __forceinline__ float2 unpack2(u64 v) {
    float2 f; asm("mov.b64 {%0, %1}, %2;" : "=f"(f.x), "=f"(f.y) : "l"(v)); return f;
}
__device__ __forceinline__ u64 add2(u64 a, u64 b) {
    u64 d; asm("add.rn.f32x2 %0, %1, %2;" : "=l"(d) : "l"(a), "l"(b)); return d;
}
__device__ __forceinline__ u64 mul2(u64 a, u64 b) {
    u64 d; asm("mul.rn.f32x2 %0, %1, %2;" : "=l"(d) : "l"(a), "l"(b)); return d;
}
__device__ __forceinline__ u64 fma2(u64 a, u64 b, u64 c) {
    u64 d; asm("fma.rn.f32x2 %0, %1, %2, %3;" : "=l"(d) : "l"(a), "l"(b), "l"(c)); return d;
}

// ---------------------------------------------------------------------------
// FPS (R2 version — measured 82us): one block/batch, 1024 threads, 8 pts/thread.
// f32x2-packed distance update; argmax via value REDUX + smem atomicMax, then
// equality search + atomicMin (reproduces lowest-index ties exactly).
// ---------------------------------------------------------------------------
extern "C" __global__ void __launch_bounds__(1024, 1)
fps_kernel(const float* __restrict__ points) {
    extern __shared__ float pts[];      // [N*3] = 96KB
    __shared__ unsigned s_maxb[K];
    __shared__ int      s_idx[K];

    const int b = blockIdx.x;
    const int t = threadIdx.x;
    const float* gp = points + (size_t)b * N * 3;

    for (int i = t; i < N * 3; i += 1024) pts[i] = gp[i];
    if (t < K) { s_maxb[t] = 0u; s_idx[t] = 0x7fffffff; }
    __syncthreads();

    u64 px2[4], py2[4], pz2[4];
    float md[8];
#pragma unroll
    for (int j = 0; j < 4; j++) {
        int nlo = t + (2 * j) * 1024;
        int nhi = t + (2 * j + 1) * 1024;
        px2[j] = pack2(pts[3 * nlo + 0], pts[3 * nhi + 0]);
        py2[j] = pack2(pts[3 * nlo + 1], pts[3 * nhi + 1]);
        pz2[j] = pack2(pts[3 * nlo + 2], pts[3 * nhi + 2]);
        md[2 * j] = CUDART_INF_F; md[2 * j + 1] = CUDART_INF_F;
    }

    int cur = 0;
    const int lane = t & 31;
    for (int k = 0; k < K; k++) {
        float cx = pts[3 * cur + 0];
        float cy = pts[3 * cur + 1];
        float cz = pts[3 * cur + 2];
        if (t == 0) {
            g_fps_idx[b * K + k] = cur;
            g_centers[(b * K + k) * 3 + 0] = cx;
            g_centers[(b * K + k) * 3 + 1] = cy;
            g_centers[(b * K + k) * 3 + 2] = cz;
        }
        u64 nc2x = pack2(-cx, -cx);
        u64 nc2y = pack2(-cy, -cy);
        u64 nc2z = pack2(-cz, -cz);
#pragma unroll
        for (int j = 0; j < 4; j++) {
            u64 dx = add2(px2[j], nc2x);
            u64 dy = add2(py2[j], nc2y);
            u64 dz = add2(pz2[j], nc2z);
            u64 d  = mul2(dx, dx);
            d = fma2(dy, dy, d);
            d = fma2(dz, dz, d);
            float2 f = unpack2(d);
            md[2 * j]     = fminf(md[2 * j],     f.x);
            md[2 * j + 1] = fminf(md[2 * j + 1], f.y);
        }
        float tv = fmaxf(fmaxf(fmaxf(md[0], md[1]), fmaxf(md[2], md[3])),
                         fmaxf(fmaxf(md[4], md[5]), fmaxf(md[6], md[7])));
        unsigned wv = __reduce_max_sync(0xffffffffu, __float_as_uint(tv));
        if (lane == 0) atomicMax(&s_maxb[k], wv);
        __syncthreads();
        const unsigned mb = s_maxb[k];
        int li = 0x7fffffff;
#pragma unroll
        for (int s = 0; s < 8; s++) {
            if (__float_as_uint(md[s]) == mb) li = min(li, t + s * 1024);
        }
        if (li != 0x7fffffff) atomicMin(&s_idx[k], li);
        __syncthreads();
        cur = s_idx[k];
    }
}

// ---------------------------------------------------------------------------
// KNN: warp-per-center streaming top-32. Each lane holds ONE of the running
// top-32 (key,idx). thresh = REDUX max of held keys. Warp handles CPW=4
// centers; CTA = 8 warps = 32 centers; 4 CTAs per batch. Points streamed
// through 32KB smem tiles. Ascending-index scan + strict '<' acceptance ==
// exact lexicographic (d2, idx) top-32 (reference top_k tie semantics).
// ---------------------------------------------------------------------------
__device__ __forceinline__ unsigned f2key(float f) {
    unsigned bits = __float_as_uint(f);
    return (bits & 0x80000000u) ? ~bits : (bits | 0x80000000u);
}

extern "C" __global__ void __launch_bounds__(256)
knn_kernel(const float* __restrict__ points) {
    __shared__ float spts[TILE * 3];    // 24KB
    __shared__ float spp[TILE];         // 8KB

    const int blk = blockIdx.x;         // 0 .. B*4-1
    const int b   = blk >> 2;
    const int cg  = blk & 3;            // center group (32 centers each)
    const int t = threadIdx.x, w = t >> 5, lane = t & 31;
    const float* gp = points + (size_t)b * N * 3;

    const int kbase = cg * 32 + w * CPW;
    float cx[CPW], cy[CPW], cz[CPW], cc[CPW];
#pragma unroll
    for (int r = 0; r < CPW; r++) {
        const float* c = &g_centers[(b * K + kbase + r) * 3];
        cx[r] = c[0]; cy[r] = c[1]; cz[r] = c[2];
        cc[r] = cx[r] * cx[r] + cy[r] * cy[r] + cz[r] * cz[r];
    }

    unsigned hk[CPW], hix[CPW], th[CPW];

    for (int tile = 0; tile < N / TILE; tile++) {
        __syncthreads();
        const float* src = gp + (size_t)tile * TILE * 3;
        for (int i = t; i < TILE * 3; i += 256) spts[i] = src[i];
        __syncthreads();
        for (int i = t; i < TILE; i += 256) {
            float x = spts[3 * i], y = spts[3 * i + 1], z = spts[3 * i + 2];
            spp[i] = x * x + y * y + z * z;
        }
        __syncthreads();

        int j0 = lane;
        if (tile == 0) {
            // seed held set with points 0..31 (the top-32 of the first 32)
            float px = spts[3 * lane], py = spts[3 * lane + 1], pz = spts[3 * lane + 2];
            float pp = spp[lane];
#pragma unroll
            for (int r = 0; r < CPW; r++) {
                float dot = cx[r] * px + cy[r] * py + cz[r] * pz;
                float d2  = (cc[r] + pp) - 2.0f * dot;
                hk[r]  = f2key(d2);
                hix[r] = (unsigned)lane;
                th[r]  = __reduce_max_sync(0xffffffffu, hk[r]);
            }
            j0 = lane + 32;
        }

        for (int j = j0; j < TILE; j += 32) {
            const int n  = tile * TILE + j;
            const int nb = n - lane;      // chunk base (uniform)
            float px = spts[3 * j], py = spts[3 * j + 1], pz = spts[3 * j + 2];
            float pp = spp[j];
#pragma unroll
            for (int r = 0; r < CPW; r++) {
                float dot = cx[r] * px + cy[r] * py + cz[r] * pz;
                float d2  = (cc[r] + pp) - 2.0f * dot;
                unsigned key = f2key(d2);
                unsigned m = __ballot_sync(0xffffffffu, key < th[r]);
                while (m) {
                    int s = __ffs(m) - 1; m &= m - 1;
                    unsigned nk = __shfl_sync(0xffffffffu, key, s);
                    if (nk < th[r]) {
                        // evict lexicographic max: key == th, max idx
                        unsigned cand = (hk[r] == th[r]) ? hix[r] : 0u;
                        unsigned mi = __reduce_max_sync(0xffffffffu, cand);
                        if (hk[r] == th[r] && hix[r] == mi) {
                            hk[r] = nk; hix[r] = (unsigned)(nb + s);
                        }
                        th[r] = __reduce_max_sync(0xffffffffu, hk[r]);
                    }
                }
            }
        }
    }

    // Output: rank each held element by (key, idx) ascending; write idx.
#pragma unroll
    for (int r = 0; r < CPW; r++) {
        u64 me = ((u64)hk[r] << 32) | hix[r];
        int rank = 0;
#pragma unroll
        for (int s = 0; s < 32; s++) {
            u64 o = __shfl_sync(0xffffffffu, me, s);
            rank += (o < me) ? 1 : 0;
        }
        g_knn[(b * K + kbase + r) * PS + rank] = (int)hix[r];
    }
}

// ---------------------------------------------------------------------------
// Epilogues — handle both plausible output layouts.
// ---------------------------------------------------------------------------
extern "C" __global__ void epilogue_i32(int* __restrict__ out, int out_size) {
    int i = blockIdx.x * 256 + threadIdx.x;
    if (i < out_size && i < B * K * PS) out[i] = g_knn[i];
}

extern "C" __global__ void epilogue_f32(float* __restrict__ out, int out_size) {
    int i = blockIdx.x * 256 + threadIdx.x;
    if (i >= out_size) return;
    if (i < B * K * PS) {
        out[i] = (float)g_knn[i];
    } else if (i < B * K * PS + B * K * 3) {
        out[i] = g_centers[i - B * K * PS];
    }
}

// ---------------------------------------------------------------------------
extern "C" void kernel_launch(void* const* d_in, const int* in_sizes, int n_in,
                              void* d_out, int out_size) {
    (void)in_sizes; (void)n_in;
    const float* points = (const float*)d_in[0];

    const int fps_smem = N * 3 * (int)sizeof(float);
    cudaFuncSetAttribute(fps_kernel,
                         cudaFuncAttributeMaxDynamicSharedMemorySize, fps_smem);

    fps_kernel<<<B, 1024, fps_smem>>>(points);
    knn_kernel<<<B * 4, 256>>>(points);

    if (out_size == B * K * PS) {
        int total = B * K * PS;
        epilogue_i32<<<(total + 255) / 256, 256>>>((int*)d_out, out_size);
    } else {
        int total = B * K * PS + B * K * 3;
        int n = total < out_size ? out_size : total;
        epilogue_f32<<<(n + 255) / 256, 256>>>((float*)d_out, out_size);
    }
}